// round 3
// baseline (speedup 1.0000x reference)
#include <cuda_runtime.h>

#define BATCH 4
#define SEQ   2048
#define EMB   768
#define NH    12
#define HD    64
#define ROWS  (BATCH*SEQ)      // 8192
#define QKSCALE 0.125f         // 64^-0.5

// -------- scratch (device globals; no allocations allowed) --------
__device__ float g_q[BATCH*NH*SEQ*HD];
__device__ float g_k[BATCH*NH*SEQ*HD];
__device__ float g_v[BATCH*NH*SEQ*HD];
__device__ float g_ctx[ROWS*EMB];

// ============================================================================
// Generic 128x128x8 SGEMM, 256 threads, 8x8 per-thread tile.
// Register-prefetch software pipeline on the k-loop.
// mode 0: C = x @ w_qkv + b_qkv, scattered into g_q/g_k/g_v as [B,H,T,hd]
// mode 1: C = g_ctx @ w_proj + b_proj -> out
// ============================================================================
__global__ __launch_bounds__(256, 2)
void sgemm_kernel(const float* __restrict__ A, const float* __restrict__ Bm,
                  const float* __restrict__ bias, float* __restrict__ out,
                  int N, int mode)
{
    __shared__ float As[8][128];   // transposed A tile: As[k][m]
    __shared__ float Bs[8][128];

    const int tid  = threadIdx.x;
    const int trow = tid >> 4;        // 0..15
    const int tcol = tid & 15;        // 0..15
    const int m0 = blockIdx.y * 128;
    const int n0 = blockIdx.x * 128;

    if (mode == 1) A = g_ctx;         // proj input is attention context

    // load mapping
    const int arow = tid >> 1;              // 0..127
    const int acol = (tid & 1) * 4;         // 0 or 4
    const int brow = tid >> 5;              // 0..7
    const int bcol = (tid & 31) * 4;        // 0..124

    const float* aptr = A  + (size_t)(m0 + arow) * EMB + acol;
    const float* bptr = Bm + (size_t)brow * N + n0 + bcol;

    float acc[8][8];
    #pragma unroll
    for (int i = 0; i < 8; i++)
        #pragma unroll
        for (int j = 0; j < 8; j++) acc[i][j] = 0.0f;

    // prologue: fetch first tile's fragments
    float4 a4 = *(const float4*)(aptr);
    float4 b4 = *(const float4*)(bptr);

    for (int kt = 0; kt < EMB; kt += 8) {
        __syncthreads();
        As[acol + 0][arow] = a4.x;
        As[acol + 1][arow] = a4.y;
        As[acol + 2][arow] = a4.z;
        As[acol + 3][arow] = a4.w;
        *(float4*)&Bs[brow][bcol] = b4;
        __syncthreads();

        // prefetch next tile while computing on this one
        if (kt + 8 < EMB) {
            a4 = *(const float4*)(aptr + kt + 8);
            b4 = *(const float4*)(bptr + (size_t)(kt + 8) * N);
        }

        #pragma unroll
        for (int k = 0; k < 8; k++) {
            float ra[8], rb[8];
            *(float4*)&ra[0] = *(float4*)&As[k][trow * 8];
            *(float4*)&ra[4] = *(float4*)&As[k][trow * 8 + 4];
            *(float4*)&rb[0] = *(float4*)&Bs[k][tcol * 8];
            *(float4*)&rb[4] = *(float4*)&Bs[k][tcol * 8 + 4];
            #pragma unroll
            for (int i = 0; i < 8; i++)
                #pragma unroll
                for (int j = 0; j < 8; j++)
                    acc[i][j] += ra[i] * rb[j];
        }
    }

    if (mode == 0) {
        // scatter into q/k/v [B, H, T, hd]
        #pragma unroll
        for (int i = 0; i < 8; i++) {
            int m = m0 + trow * 8 + i;
            int b = m / SEQ, t = m % SEQ;
            #pragma unroll
            for (int j = 0; j < 8; j++) {
                int n = n0 + tcol * 8 + j;
                float v = acc[i][j] + bias[n];
                int c = n / EMB;
                int r = n - c * EMB;
                int h = r >> 6, d = r & 63;
                float* dst = (c == 0) ? g_q : (c == 1) ? g_k : g_v;
                dst[(((size_t)b * NH + h) * SEQ + t) * HD + d] = v;
            }
        }
    } else {
        #pragma unroll
        for (int i = 0; i < 8; i++) {
            int m = m0 + trow * 8 + i;
            #pragma unroll
            for (int j4 = 0; j4 < 8; j4 += 4) {
                int n = n0 + tcol * 8 + j4;
                float4 o;
                o.x = acc[i][j4 + 0] + bias[n + 0];
                o.y = acc[i][j4 + 1] + bias[n + 1];
                o.z = acc[i][j4 + 2] + bias[n + 2];
                o.w = acc[i][j4 + 3] + bias[n + 3];
                *(float4*)&out[(size_t)m * EMB + n] = o;
            }
        }
    }
}

// ============================================================================
// Flash attention: 64-query tile per CTA, 64-key tiles, hd=64.
// 256 threads as 16x16; each thread owns a 4x4 micro-tile of S and of O.
// Online softmax state (m,l) kept redundantly per 16-lane row group.
// smem stride 68 (pad 4) keeps float4 access and tames transpose conflicts.
// ============================================================================
#define FSTR 68
#define FLASH_SMEM (4 * 64 * FSTR * 4)

__global__ __launch_bounds__(256, 2)
void flash_attn_kernel()
{
    extern __shared__ float sm[];
    float* Qs = sm;                    // [64][68]  (pre-scaled by QKSCALE)
    float* Kt = sm + 64 * FSTR;        // [d][j]    transposed K tile
    float* Vs = sm + 2 * 64 * FSTR;    // [j][d]
    float* Ps = sm + 3 * 64 * FSTR;    // [row][j]

    const int tid = threadIdx.x;
    const int ty = tid >> 4;           // 0..15 -> rows ty*4..ty*4+3
    const int tx = tid & 15;           // 0..15 -> cols tx*4..tx*4+3
    const int b = blockIdx.z, h = blockIdx.y;
    const int q0 = blockIdx.x * 64;

    const size_t head_off = ((size_t)b * NH + h) * SEQ * HD;
    const float* qp = g_q + head_off;
    const float* kp = g_k + head_off;
    const float* vp = g_v + head_off;

    // load Q tile (scaled)
    #pragma unroll
    for (int it = 0; it < 4; it++) {
        int idx = it * 256 + tid;
        int r = idx >> 4, c4 = (idx & 15) * 4;
        float4 q4 = *(const float4*)(qp + (size_t)(q0 + r) * HD + c4);
        q4.x *= QKSCALE; q4.y *= QKSCALE; q4.z *= QKSCALE; q4.w *= QKSCALE;
        *(float4*)&Qs[r * FSTR + c4] = q4;
    }

    float m_run[4], l_run[4], acc[4][4];
    #pragma unroll
    for (int i = 0; i < 4; i++) {
        m_run[i] = -1e30f; l_run[i] = 0.0f;
        #pragma unroll
        for (int j = 0; j < 4; j++) acc[i][j] = 0.0f;
    }

    for (int k0 = 0; k0 < SEQ; k0 += 64) {
        __syncthreads();   // protect Kt/Vs/Ps (and first-iter Qs) before rewrite
        #pragma unroll
        for (int it = 0; it < 4; it++) {
            int idx = it * 256 + tid;
            int r = idx >> 4, c4 = (idx & 15) * 4;
            float4 k4 = *(const float4*)(kp + (size_t)(k0 + r) * HD + c4);
            Kt[(c4 + 0) * FSTR + r] = k4.x;
            Kt[(c4 + 1) * FSTR + r] = k4.y;
            Kt[(c4 + 2) * FSTR + r] = k4.z;
            Kt[(c4 + 3) * FSTR + r] = k4.w;
            float4 v4 = *(const float4*)(vp + (size_t)(k0 + r) * HD + c4);
            *(float4*)&Vs[r * FSTR + c4] = v4;
        }
        __syncthreads();

        // ---- S = Qs @ Kt  (64x64x64), 4x4 per thread ----
        float s[4][4];
        #pragma unroll
        for (int i = 0; i < 4; i++)
            #pragma unroll
            for (int j = 0; j < 4; j++) s[i][j] = 0.0f;

        #pragma unroll
        for (int d4 = 0; d4 < 16; d4++) {
            float a[4][4], bv[4][4];
            #pragma unroll
            for (int i = 0; i < 4; i++)
                *(float4*)a[i] = *(const float4*)&Qs[(ty * 4 + i) * FSTR + d4 * 4];
            #pragma unroll
            for (int dd = 0; dd < 4; dd++)
                *(float4*)bv[dd] = *(const float4*)&Kt[(d4 * 4 + dd) * FSTR + tx * 4];
            #pragma unroll
            for (int i = 0; i < 4; i++)
                #pragma unroll
                for (int dd = 0; dd < 4; dd++)
                    #pragma unroll
                    for (int j = 0; j < 4; j++)
                        s[i][j] += a[i][dd] * bv[dd][j];
        }

        // ---- online softmax over the 64-wide row (16 lanes x 4 cols) ----
        #pragma unroll
        for (int i = 0; i < 4; i++) {
            float mx = fmaxf(fmaxf(s[i][0], s[i][1]), fmaxf(s[i][2], s[i][3]));
            #pragma unroll
            for (int o = 8; o >= 1; o >>= 1)
                mx = fmaxf(mx, __shfl_xor_sync(0xffffffffu, mx, o));
            float m_new = fmaxf(m_run[i], mx);
            float alpha = __expf(m_run[i] - m_new);
            m_run[i] = m_new;
            float rs = 0.0f;
            #pragma unroll
            for (int j = 0; j < 4; j++) {
                s[i][j] = __expf(s[i][j] - m_new);
                rs += s[i][j];
            }
            #pragma unroll
            for (int o = 8; o >= 1; o >>= 1)
                rs += __shfl_xor_sync(0xffffffffu, rs, o);
            l_run[i] = l_run[i] * alpha + rs;
            #pragma unroll
            for (int j = 0; j < 4; j++) acc[i][j] *= alpha;
            *(float4*)&Ps[(ty * 4 + i) * FSTR + tx * 4] = *(float4*)s[i];
        }
        __syncthreads();

        // ---- O += Ps @ Vs  (64x64x64) ----
        #pragma unroll
        for (int k4 = 0; k4 < 16; k4++) {
            float a[4][4], bv[4][4];
            #pragma unroll
            for (int i = 0; i < 4; i++)
                *(float4*)a[i] = *(const float4*)&Ps[(ty * 4 + i) * FSTR + k4 * 4];
            #pragma unroll
            for (int kk = 0; kk < 4; kk++)
                *(float4*)bv[kk] = *(const float4*)&Vs[(k4 * 4 + kk) * FSTR + tx * 4];
            #pragma unroll
            for (int i = 0; i < 4; i++)
                #pragma unroll
                for (int kk = 0; kk < 4; kk++)
                    #pragma unroll
                    for (int j = 0; j < 4; j++)
                        acc[i][j] += a[i][kk] * bv[kk][j];
        }
    }

    // finalize: divide by l, write ctx in [B, T, EMB] layout
    #pragma unroll
    for (int i = 0; i < 4; i++) {
        float inv = 1.0f / l_run[i];
        int t = q0 + ty * 4 + i;
        float4 o;
        o.x = acc[i][0] * inv; o.y = acc[i][1] * inv;
        o.z = acc[i][2] * inv; o.w = acc[i][3] * inv;
        *(float4*)&g_ctx[((size_t)b * SEQ + t) * EMB + h * HD + tx * 4] = o;
    }
}

// ============================================================================
extern "C" void kernel_launch(void* const* d_in, const int* in_sizes, int n_in,
                              void* d_out, int out_size)
{
    const float* x      = (const float*)d_in[0];
    const float* w_qkv  = (const float*)d_in[1];
    const float* b_qkv  = (const float*)d_in[2];
    const float* w_proj = (const float*)d_in[3];
    const float* b_proj = (const float*)d_in[4];
    float* out = (float*)d_out;

    (void)cudaFuncSetAttribute(flash_attn_kernel,
                               cudaFuncAttributeMaxDynamicSharedMemorySize,
                               FLASH_SMEM);

    // 1) QKV GEMM + bias, scattered to [B,H,T,hd]
    sgemm_kernel<<<dim3(3 * EMB / 128, ROWS / 128), 256>>>(
        x, w_qkv, b_qkv, nullptr, 3 * EMB, 0);

    // 2) flash attention -> g_ctx [B,T,EMB]
    flash_attn_kernel<<<dim3(SEQ / 64, NH, BATCH), 256, FLASH_SMEM>>>();

    // 3) proj GEMM + bias -> out
    sgemm_kernel<<<dim3(EMB / 128, ROWS / 128), 256>>>(
        nullptr, w_proj, b_proj, out, EMB, 1);
}